// round 2
// baseline (speedup 1.0000x reference)
#include <cuda_runtime.h>
#include <math.h>

#define NND 50000
#define NE  800000
#define HIDN 128
#define NODE_IN 32
#define EDGE_IN 16
#define CIN 272        // 2*HID + EDGE_IN
#define CIN_PAD 276
#define UIN 256        // 2*HID
#define UIN_PAD 260
#define HPAD 132
#define XPAD 36
#define TE 32
#define TN 32

typedef unsigned long long ull;

// ---------------- persistent scratch (no allocations allowed) ----------------
__device__ float g_h[NND * HIDN];
__device__ float g_aggr[NND * HIDN];
__device__ float g_invd[NND];
__device__ int   g_cnt[NND];
__device__ int   g_is64;

// ---------------- packed f32x2 helpers ----------------
__device__ __forceinline__ ull fma2(ull a, ull b, ull c) {
    ull d;
    asm("fma.rn.f32x2 %0, %1, %2, %3;" : "=l"(d) : "l"(a), "l"(b), "l"(c));
    return d;
}
__device__ __forceinline__ ull dup2(float a) {
    ull d; unsigned r = __float_as_uint(a);
    asm("mov.b64 %0, {%1, %1};" : "=l"(d) : "r"(r));
    return d;
}
__device__ __forceinline__ float2 unpack2(ull v) {
    unsigned lo, hi;
    asm("mov.b64 {%0, %1}, %2;" : "=r"(lo), "=r"(hi) : "l"(v));
    return make_float2(__uint_as_float(lo), __uint_as_float(hi));
}

// ---------------- edge index access (int32 or int64, runtime-detected) ------
__device__ __forceinline__ void load_edge(const void* ei, int e, int& s, int& t) {
    if (g_is64) {
        const long long* p = (const long long*)ei;
        s = (int)p[e];
        t = (int)p[NE + e];
    } else {
        const int* p = (const int*)ei;
        s = p[e];
        t = p[NE + e];
    }
}

// ---------------- setup kernels ----------------
__global__ void init_kernel() {
    int i = blockIdx.x * blockDim.x + threadIdx.x;
    int stride = gridDim.x * blockDim.x;
    if (i == 0) g_is64 = 1;
    for (int j = i; j < NND; j += stride) g_cnt[j] = 0;
    for (int j = i; j < NND * HIDN; j += stride) g_aggr[j] = 0.f;
}

// If data is int64 (values < 2^31), every odd 32-bit word of the first NE
// elements is 0. If int32, those words are random node indices (some nonzero).
__global__ void detect_kernel(const unsigned* w) {
    int stride = gridDim.x * blockDim.x;
    bool nz = false;
    for (int i = blockIdx.x * blockDim.x + threadIdx.x; i < NE; i += stride)
        nz |= (w[2 * i + 1] != 0u);
    if (nz) g_is64 = 0;
}

__global__ void count_kernel(const void* ei) {
    int stride = gridDim.x * blockDim.x;
    for (int e = blockIdx.x * blockDim.x + threadIdx.x; e < NE; e += stride) {
        int s, t; load_edge(ei, e, s, t);
        atomicAdd(&g_cnt[t], 1);
    }
}

__global__ void inv_kernel() {
    int n = blockIdx.x * blockDim.x + threadIdx.x;
    if (n < NND) g_invd[n] = 1.f / fmaxf((float)g_cnt[n], 1.f);
}

// ---------------- layernorm + store helper (operates on s_out[TN][HPAD]) ----
__device__ __forceinline__ void ln_store(float (*s_out)[HPAD], int nb,
                                         const float* gw, const float* gb,
                                         bool zero_aggr) {
    int tid = threadIdx.x;
    int nn = tid >> 3;      // node slot 0..31
    int p  = tid & 7;       // 8 threads per node, 16 channels each
    int n  = nb + nn;
    float vals[16];
    float sum = 0.f, sq = 0.f;
#pragma unroll
    for (int i = 0; i < 4; i++) {
        float4 t4 = *(float4*)&s_out[nn][16 * p + 4 * i];
        vals[4*i+0] = t4.x; vals[4*i+1] = t4.y; vals[4*i+2] = t4.z; vals[4*i+3] = t4.w;
        sum += t4.x + t4.y + t4.z + t4.w;
        sq  += t4.x*t4.x + t4.y*t4.y + t4.z*t4.z + t4.w*t4.w;
    }
#pragma unroll
    for (int off = 4; off; off >>= 1) {
        sum += __shfl_xor_sync(0xffffffffu, sum, off);
        sq  += __shfl_xor_sync(0xffffffffu, sq,  off);
    }
    float mean = sum * (1.f / 128.f);
    float var  = sq * (1.f / 128.f) - mean * mean;
    float rs   = rsqrtf(var + 1e-5f);
    if (n < NND) {
#pragma unroll
        for (int i = 0; i < 4; i++) {
            int c = 16 * p + 4 * i;
            float4 o;
            o.x = (vals[4*i+0] - mean) * rs * gw[c + 0] + gb[c + 0];
            o.y = (vals[4*i+1] - mean) * rs * gw[c + 1] + gb[c + 1];
            o.z = (vals[4*i+2] - mean) * rs * gw[c + 2] + gb[c + 2];
            o.w = (vals[4*i+3] - mean) * rs * gw[c + 3] + gb[c + 3];
            *(float4*)&g_h[n * HIDN + c] = o;
            if (zero_aggr)
                *(float4*)&g_aggr[n * HIDN + c] = make_float4(0.f, 0.f, 0.f, 0.f);
        }
    }
}

// ---------------- encoder: h = LN(relu(x @ W + b)) ----------------
__global__ __launch_bounds__(256) void encoder_kernel(const float* x, const float* W,
                                                      const float* b, const float* gw,
                                                      const float* gb) {
    __shared__ float s_in[TN][XPAD];
    __shared__ float s_out[TN][HPAD];
    int tid = threadIdx.x, lane = tid & 31, w = tid >> 5;
    int nb = blockIdx.x * TN;
    for (int j = w; j < TN; j += 8) {
        int n = nb + j;
        if (lane < 8) {
            float4 v = make_float4(0.f, 0.f, 0.f, 0.f);
            if (n < NND) v = *(const float4*)&x[n * NODE_IN + 4 * lane];
            *(float4*)&s_in[j][4 * lane] = v;
        }
    }
    __syncthreads();
    int cg = tid & 31, c0 = 4 * cg, eg = tid >> 5, e0 = 4 * eg;
    ull acc[4][2];
    {
        ull b01 = *(const ull*)(b + c0), b23 = *(const ull*)(b + c0 + 2);
#pragma unroll
        for (int i = 0; i < 4; i++) { acc[i][0] = b01; acc[i][1] = b23; }
    }
#pragma unroll
    for (int k = 0; k < NODE_IN; k++) {
        ulonglong2 wv = *(const ulonglong2*)(W + k * HIDN + c0);
#pragma unroll
        for (int i = 0; i < 4; i++) {
            ull a = dup2(s_in[e0 + i][k]);
            acc[i][0] = fma2(a, wv.x, acc[i][0]);
            acc[i][1] = fma2(a, wv.y, acc[i][1]);
        }
    }
#pragma unroll
    for (int i = 0; i < 4; i++) {
        float2 v0 = unpack2(acc[i][0]), v1 = unpack2(acc[i][1]);
        s_out[e0 + i][c0 + 0] = fmaxf(v0.x, 0.f);
        s_out[e0 + i][c0 + 1] = fmaxf(v0.y, 0.f);
        s_out[e0 + i][c0 + 2] = fmaxf(v1.x, 0.f);
        s_out[e0 + i][c0 + 3] = fmaxf(v1.y, 0.f);
    }
    __syncthreads();
    ln_store(s_out, nb, gw, gb, false);
}

// ---------------- fused edge MLP + mean-aggregation scatter ----------------
__global__ __launch_bounds__(256) void edge_kernel(const void* ei, const float* ea,
                                                   const float* W1, const float* b1,
                                                   const float* W2, const float* b2) {
    __shared__ float s_in[TE][CIN_PAD];
    __shared__ float s_hid[TE][HPAD];
    __shared__ int   s_t[TE];
    int tid = threadIdx.x, lane = tid & 31, w = tid >> 5;
    int eb = blockIdx.x * TE;
    for (int j = w; j < TE; j += 8) {
        int e = eb + j;
        int s, t; load_edge(ei, e, s, t);
        if (lane == 0) s_t[j] = t;
        *(float4*)&s_in[j][4 * lane]        = *(const float4*)&g_h[t * HIDN + 4 * lane];
        *(float4*)&s_in[j][HIDN + 4 * lane] = *(const float4*)&g_h[s * HIDN + 4 * lane];
        if (lane < 4)
            *(float4*)&s_in[j][2 * HIDN + 4 * lane] = *(const float4*)&ea[e * EDGE_IN + 4 * lane];
    }
    __syncthreads();
    int cg = tid & 31, c0 = 4 * cg, eg = tid >> 5, e0 = 4 * eg;
    ull acc[4][2];
    {
        ull b01 = *(const ull*)(b1 + c0), b23 = *(const ull*)(b1 + c0 + 2);
#pragma unroll
        for (int i = 0; i < 4; i++) { acc[i][0] = b01; acc[i][1] = b23; }
    }
#pragma unroll 4
    for (int k = 0; k < CIN; k++) {
        ulonglong2 wv = *(const ulonglong2*)(W1 + k * HIDN + c0);
#pragma unroll
        for (int i = 0; i < 4; i++) {
            ull a = dup2(s_in[e0 + i][k]);
            acc[i][0] = fma2(a, wv.x, acc[i][0]);
            acc[i][1] = fma2(a, wv.y, acc[i][1]);
        }
    }
#pragma unroll
    for (int i = 0; i < 4; i++) {
        float2 v0 = unpack2(acc[i][0]), v1 = unpack2(acc[i][1]);
        float2 r0 = make_float2(fmaxf(v0.x, 0.f), fmaxf(v0.y, 0.f));
        float2 r1 = make_float2(fmaxf(v1.x, 0.f), fmaxf(v1.y, 0.f));
        *(float2*)&s_hid[e0 + i][c0 + 0] = r0;
        *(float2*)&s_hid[e0 + i][c0 + 2] = r1;
    }
    __syncthreads();
    ull acc2[4][2];
    {
        ull b01 = *(const ull*)(b2 + c0), b23 = *(const ull*)(b2 + c0 + 2);
#pragma unroll
        for (int i = 0; i < 4; i++) { acc2[i][0] = b01; acc2[i][1] = b23; }
    }
#pragma unroll 4
    for (int k = 0; k < HIDN; k++) {
        ulonglong2 wv = *(const ulonglong2*)(W2 + k * HIDN + c0);
#pragma unroll
        for (int i = 0; i < 4; i++) {
            ull a = dup2(s_hid[e0 + i][k]);
            acc2[i][0] = fma2(a, wv.x, acc2[i][0]);
            acc2[i][1] = fma2(a, wv.y, acc2[i][1]);
        }
    }
#pragma unroll
    for (int i = 0; i < 4; i++) {
        int t = s_t[e0 + i];
        float* dst = &g_aggr[t * HIDN];
        float2 v0 = unpack2(acc2[i][0]), v1 = unpack2(acc2[i][1]);
        atomicAdd(dst + c0 + 0, v0.x);
        atomicAdd(dst + c0 + 1, v0.y);
        atomicAdd(dst + c0 + 2, v1.x);
        atomicAdd(dst + c0 + 3, v1.y);
    }
}

// ---------------- node update: h = LN(h + MLP([h, aggr/deg])) ----------------
__global__ __launch_bounds__(256) void update_kernel(const float* W1, const float* b1,
                                                     const float* W2, const float* b2,
                                                     const float* gw, const float* gb) {
    __shared__ float s_in[TN][UIN_PAD];
    __shared__ float s_hid[TN][HPAD];
    __shared__ float s_out[TN][HPAD];
    int tid = threadIdx.x, lane = tid & 31, w = tid >> 5;
    int nb = blockIdx.x * TN;
    for (int j = w; j < TN; j += 8) {
        int n = nb + j;
        if (n < NND) {
            float invd = g_invd[n];
            float4 hv = *(const float4*)&g_h[n * HIDN + 4 * lane];
            float4 av = *(const float4*)&g_aggr[n * HIDN + 4 * lane];
            av.x *= invd; av.y *= invd; av.z *= invd; av.w *= invd;
            *(float4*)&s_in[j][4 * lane] = hv;
            *(float4*)&s_in[j][HIDN + 4 * lane] = av;
        } else {
            *(float4*)&s_in[j][4 * lane] = make_float4(0.f, 0.f, 0.f, 0.f);
            *(float4*)&s_in[j][HIDN + 4 * lane] = make_float4(0.f, 0.f, 0.f, 0.f);
        }
    }
    __syncthreads();
    int cg = tid & 31, c0 = 4 * cg, eg = tid >> 5, e0 = 4 * eg;
    ull acc[4][2];
    {
        ull b01 = *(const ull*)(b1 + c0), b23 = *(const ull*)(b1 + c0 + 2);
#pragma unroll
        for (int i = 0; i < 4; i++) { acc[i][0] = b01; acc[i][1] = b23; }
    }
#pragma unroll 4
    for (int k = 0; k < UIN; k++) {
        ulonglong2 wv = *(const ulonglong2*)(W1 + k * HIDN + c0);
#pragma unroll
        for (int i = 0; i < 4; i++) {
            ull a = dup2(s_in[e0 + i][k]);
            acc[i][0] = fma2(a, wv.x, acc[i][0]);
            acc[i][1] = fma2(a, wv.y, acc[i][1]);
        }
    }
#pragma unroll
    for (int i = 0; i < 4; i++) {
        float2 v0 = unpack2(acc[i][0]), v1 = unpack2(acc[i][1]);
        float2 r0 = make_float2(fmaxf(v0.x, 0.f), fmaxf(v0.y, 0.f));
        float2 r1 = make_float2(fmaxf(v1.x, 0.f), fmaxf(v1.y, 0.f));
        *(float2*)&s_hid[e0 + i][c0 + 0] = r0;
        *(float2*)&s_hid[e0 + i][c0 + 2] = r1;
    }
    __syncthreads();
    ull acc2[4][2];
    {
        ull b01 = *(const ull*)(b2 + c0), b23 = *(const ull*)(b2 + c0 + 2);
#pragma unroll
        for (int i = 0; i < 4; i++) { acc2[i][0] = b01; acc2[i][1] = b23; }
    }
#pragma unroll 4
    for (int k = 0; k < HIDN; k++) {
        ulonglong2 wv = *(const ulonglong2*)(W2 + k * HIDN + c0);
#pragma unroll
        for (int i = 0; i < 4; i++) {
            ull a = dup2(s_hid[e0 + i][k]);
            acc2[i][0] = fma2(a, wv.x, acc2[i][0]);
            acc2[i][1] = fma2(a, wv.y, acc2[i][1]);
        }
    }
#pragma unroll
    for (int i = 0; i < 4; i++) {
        float2 v0 = unpack2(acc2[i][0]), v1 = unpack2(acc2[i][1]);
        // residual: + h (still intact in s_in[.][0:128])
        s_out[e0 + i][c0 + 0] = v0.x + s_in[e0 + i][c0 + 0];
        s_out[e0 + i][c0 + 1] = v0.y + s_in[e0 + i][c0 + 1];
        s_out[e0 + i][c0 + 2] = v1.x + s_in[e0 + i][c0 + 2];
        s_out[e0 + i][c0 + 3] = v1.y + s_in[e0 + i][c0 + 3];
    }
    __syncthreads();
    ln_store(s_out, nb, gw, gb, true);  // also zero g_aggr for next layer
}

// ---------------- head: out = h @ head_W + head_b ----------------
__global__ __launch_bounds__(256) void head_kernel(const float* W, const float* b,
                                                   float* out) {
    __shared__ float s_in[TN][HPAD];
    int tid = threadIdx.x, lane = tid & 31, w = tid >> 5;
    int nb = blockIdx.x * TN;
    for (int j = w; j < TN; j += 8) {
        int n = nb + j;
        float4 v = make_float4(0.f, 0.f, 0.f, 0.f);
        if (n < NND) v = *(const float4*)&g_h[n * HIDN + 4 * lane];
        *(float4*)&s_in[j][4 * lane] = v;
    }
    __syncthreads();
    int cg = tid & 31, c0 = 4 * cg, eg = tid >> 5, e0 = 4 * eg;
    ull acc[4][2];
    {
        ull b01 = *(const ull*)(b + c0), b23 = *(const ull*)(b + c0 + 2);
#pragma unroll
        for (int i = 0; i < 4; i++) { acc[i][0] = b01; acc[i][1] = b23; }
    }
#pragma unroll 4
    for (int k = 0; k < HIDN; k++) {
        ulonglong2 wv = *(const ulonglong2*)(W + k * HIDN + c0);
#pragma unroll
        for (int i = 0; i < 4; i++) {
            ull a = dup2(s_in[e0 + i][k]);
            acc[i][0] = fma2(a, wv.x, acc[i][0]);
            acc[i][1] = fma2(a, wv.y, acc[i][1]);
        }
    }
#pragma unroll
    for (int i = 0; i < 4; i++) {
        int n = nb + e0 + i;
        if (n < NND) {
            float2 v0 = unpack2(acc[i][0]), v1 = unpack2(acc[i][1]);
            *(float2*)&out[n * HIDN + c0 + 0] = v0;
            *(float2*)&out[n * HIDN + c0 + 2] = v1;
        }
    }
}

// ---------------- launch ----------------
extern "C" void kernel_launch(void* const* d_in, const int* in_sizes, int n_in,
                              void* d_out, int out_size) {
    const float* x      = (const float*)d_in[0];
    const void*  ei     = d_in[1];
    const float* ea     = (const float*)d_in[2];
    const float* enc_W  = (const float*)d_in[3];
    const float* enc_b  = (const float*)d_in[4];
    const float* enc_g  = (const float*)d_in[5];
    const float* enc_be = (const float*)d_in[6];
    const float* msg_W1 = (const float*)d_in[7];
    const float* msg_b1 = (const float*)d_in[8];
    const float* msg_W2 = (const float*)d_in[9];
    const float* msg_b2 = (const float*)d_in[10];
    const float* upd_W1 = (const float*)d_in[11];
    const float* upd_b1 = (const float*)d_in[12];
    const float* upd_W2 = (const float*)d_in[13];
    const float* upd_b2 = (const float*)d_in[14];
    const float* ln_g   = (const float*)d_in[15];
    const float* ln_be  = (const float*)d_in[16];
    const float* head_W = (const float*)d_in[17];
    const float* head_b = (const float*)d_in[18];
    float* out = (float*)d_out;

    init_kernel<<<256, 256>>>();
    detect_kernel<<<256, 256>>>((const unsigned*)ei);
    count_kernel<<<512, 256>>>(ei);
    inv_kernel<<<(NND + 255) / 256, 256>>>();

    int nblk = (NND + TN - 1) / TN;
    encoder_kernel<<<nblk, 256>>>(x, enc_W, enc_b, enc_g, enc_be);

    for (int l = 0; l < 2; l++) {
        edge_kernel<<<NE / TE, 256>>>(ei, ea,
                                      msg_W1 + l * CIN * HIDN, msg_b1 + l * HIDN,
                                      msg_W2 + l * HIDN * HIDN, msg_b2 + l * HIDN);
        update_kernel<<<nblk, 256>>>(upd_W1 + l * UIN * HIDN, upd_b1 + l * HIDN,
                                     upd_W2 + l * HIDN * HIDN, upd_b2 + l * HIDN,
                                     ln_g + l * HIDN, ln_be + l * HIDN);
    }
    head_kernel<<<nblk, 256>>>(head_W, head_b, out);
}

// round 3
// speedup vs baseline: 1.1375x; 1.1375x over previous
#include <cuda_runtime.h>
#include <math.h>

#define NND 50000
#define NE  800000
#define HIDN 128
#define NODE_IN 32
#define EDGE_IN 16
#define CIN 272        // 2*HID + EDGE_IN
#define UIN 256        // 2*HID
#define HPAD 132
#define XPAD 36
#define TN 32

typedef unsigned long long ull;

// ---------------- persistent scratch ----------------
__device__ float g_h[NND * HIDN];
__device__ float g_aggr[NND * HIDN];
__device__ float g_invd[NND];
__device__ int   g_cnt[NND];
__device__ int   g_is64;

// ---------------- packed f32x2 helpers ----------------
__device__ __forceinline__ ull fma2(ull a, ull b, ull c) {
    ull d;
    asm("fma.rn.f32x2 %0, %1, %2, %3;" : "=l"(d) : "l"(a), "l"(b), "l"(c));
    return d;
}
__device__ __forceinline__ ull dup2(float a) {
    ull d; unsigned r = __float_as_uint(a);
    asm("mov.b64 %0, {%1, %1};" : "=l"(d) : "r"(r));
    return d;
}
__device__ __forceinline__ float2 unpack2(ull v) {
    unsigned lo, hi;
    asm("mov.b64 {%0, %1}, %2;" : "=r"(lo), "=r"(hi) : "l"(v));
    return make_float2(__uint_as_float(lo), __uint_as_float(hi));
}

// ---------------- async copy helpers ----------------
__device__ __forceinline__ void cp16(float* dst_smem, const float* src) {
    unsigned d = (unsigned)__cvta_generic_to_shared(dst_smem);
    asm volatile("cp.async.ca.shared.global [%0], [%1], 16;" :: "r"(d), "l"(src));
}
__device__ __forceinline__ void cp_commit() {
    asm volatile("cp.async.commit_group;");
}
template<int N> __device__ __forceinline__ void cp_wait() {
    asm volatile("cp.async.wait_group %0;" :: "n"(N));
}
// stage one 16x128 fp32 W chunk (2048 floats) with 256 threads
__device__ __forceinline__ void stage_w(float* dst, const float* src, int tid) {
    int o = tid * 8;
    cp16(dst + o, src + o);
    cp16(dst + o + 4, src + o + 4);
}

// vector reduction into global (fp32 x4)
__device__ __forceinline__ void red4(float* addr, float4 v) {
    asm volatile("red.global.add.v4.f32 [%0], {%1, %2, %3, %4};"
                 :: "l"(addr), "f"(v.x), "f"(v.y), "f"(v.z), "f"(v.w) : "memory");
}

// ---------------- edge index (int32/int64 runtime-detected) ----------------
__device__ __forceinline__ void load_edge(const void* ei, int e, int& s, int& t) {
    if (g_is64) {
        const long long* p = (const long long*)ei;
        s = (int)p[e];
        t = (int)p[NE + e];
    } else {
        const int* p = (const int*)ei;
        s = p[e];
        t = p[NE + e];
    }
}

// ---------------- setup kernels ----------------
__global__ void init_kernel() {
    int i = blockIdx.x * blockDim.x + threadIdx.x;
    int stride = gridDim.x * blockDim.x;
    if (i == 0) g_is64 = 1;
    for (int j = i; j < NND; j += stride) g_cnt[j] = 0;
    for (int j = i; j < NND * HIDN; j += stride) g_aggr[j] = 0.f;
}
__global__ void detect_kernel(const unsigned* w) {
    int stride = gridDim.x * blockDim.x;
    bool nz = false;
    for (int i = blockIdx.x * blockDim.x + threadIdx.x; i < NE; i += stride)
        nz |= (w[2 * i + 1] != 0u);
    if (nz) g_is64 = 0;
}
__global__ void count_kernel(const void* ei) {
    int stride = gridDim.x * blockDim.x;
    for (int e = blockIdx.x * blockDim.x + threadIdx.x; e < NE; e += stride) {
        int s, t; load_edge(ei, e, s, t);
        atomicAdd(&g_cnt[t], 1);
    }
}
__global__ void inv_kernel() {
    int n = blockIdx.x * blockDim.x + threadIdx.x;
    if (n < NND) g_invd[n] = 1.f / fmaxf((float)g_cnt[n], 1.f);
}

// ============================================================================
// Fused edge MLP + scatter.  64 edges/block, 256 threads.
// Register tile: 4 edges x 8 channels/thread.  W staged in smem (cp.async x2).
// SMEM: s_in[64][272] (69632B) | wbuf[2][2048] (16384B) | s_t[64]  => 86272B
// s_hid[64][128] aliases s_in.
// ============================================================================
#define EDGE_SMEM (64*272*4 + 2*2048*4 + 64*4)

__global__ void __launch_bounds__(256) edge_kernel2(
        const void* ei, const float* ea,
        const float* W1, const float* b1,
        const float* W2, const float* b2) {
    extern __shared__ float sm[];
    float* s_in  = sm;                       // [64][272]
    float* wb    = sm + 64 * 272;            // [2][2048]
    int*   s_t   = (int*)(sm + 64 * 272 + 2 * 2048);
    float* s_hid = sm;                       // alias [64][128]

    int tid = threadIdx.x, lane = tid & 31, warp = tid >> 5;
    int eb = blockIdx.x * 64;

    // prefetch W1 chunk 0 (overlaps gather)
    stage_w(wb, W1, tid); cp_commit();

    // gather [x_i | x_j | edge_attr]
    for (int j = warp; j < 64; j += 8) {
        int e = eb + j, s, t;
        load_edge(ei, e, s, t);
        if (lane == 0) s_t[j] = t;
        *(float4*)&s_in[j * 272 + 4 * lane]       = *(const float4*)&g_h[t * HIDN + 4 * lane];
        *(float4*)&s_in[j * 272 + 128 + 4 * lane] = *(const float4*)&g_h[s * HIDN + 4 * lane];
        if (lane < 4)
            *(float4*)&s_in[j * 272 + 256 + 4 * lane] =
                *(const float4*)&ea[(size_t)e * EDGE_IN + 4 * lane];
    }

    int cg = tid & 15, egp = tid >> 4;
    int c0 = 8 * cg, e0 = 4 * egp;

    // ---------------- GEMM1: [64,272] @ [272,128], relu ----------------
    ull acc[4][4];
    {
        ulonglong2 bA = *(const ulonglong2*)(b1 + c0);
        ulonglong2 bB = *(const ulonglong2*)(b1 + c0 + 4);
#pragma unroll
        for (int i = 0; i < 4; i++) {
            acc[i][0] = bA.x; acc[i][1] = bA.y; acc[i][2] = bB.x; acc[i][3] = bB.y;
        }
    }
    for (int c = 0; c < 17; c++) {
        if (c < 16) {
            stage_w(wb + ((c + 1) & 1) * 2048, W1 + (c + 1) * 2048, tid);
            cp_commit(); cp_wait<1>();
        } else cp_wait<0>();
        __syncthreads();
        const float* w = wb + (c & 1) * 2048;
        int kb = c * 16;
#pragma unroll
        for (int k4 = 0; k4 < 16; k4 += 4) {
            float4 av[4];
#pragma unroll
            for (int i = 0; i < 4; i++)
                av[i] = *(const float4*)&s_in[(e0 + i) * 272 + kb + k4];
#pragma unroll
            for (int kk = 0; kk < 4; kk++) {
                const float* wr = w + (k4 + kk) * 128 + c0;
                ulonglong2 w0 = *(const ulonglong2*)(wr);
                ulonglong2 w1 = *(const ulonglong2*)(wr + 4);
#pragma unroll
                for (int i = 0; i < 4; i++) {
                    float a = (kk == 0) ? av[i].x : (kk == 1) ? av[i].y :
                              (kk == 2) ? av[i].z : av[i].w;
                    ull ad = dup2(a);
                    acc[i][0] = fma2(ad, w0.x, acc[i][0]);
                    acc[i][1] = fma2(ad, w0.y, acc[i][1]);
                    acc[i][2] = fma2(ad, w1.x, acc[i][2]);
                    acc[i][3] = fma2(ad, w1.y, acc[i][3]);
                }
            }
        }
        __syncthreads();
    }

    // prefetch W2 chunk 0 (buffer 0 free after final sync above)
    stage_w(wb, W2, tid); cp_commit();

    // relu -> s_hid (aliases s_in; all reads of s_in completed at last sync)
#pragma unroll
    for (int i = 0; i < 4; i++) {
        float2 p0 = unpack2(acc[i][0]), p1 = unpack2(acc[i][1]);
        float2 p2 = unpack2(acc[i][2]), p3 = unpack2(acc[i][3]);
        *(float4*)&s_hid[(e0 + i) * 128 + c0] =
            make_float4(fmaxf(p0.x, 0.f), fmaxf(p0.y, 0.f), fmaxf(p1.x, 0.f), fmaxf(p1.y, 0.f));
        *(float4*)&s_hid[(e0 + i) * 128 + c0 + 4] =
            make_float4(fmaxf(p2.x, 0.f), fmaxf(p2.y, 0.f), fmaxf(p3.x, 0.f), fmaxf(p3.y, 0.f));
    }

    // ---------------- GEMM2: [64,128] @ [128,128] ----------------
    ull acc2[4][4];
    {
        ulonglong2 bA = *(const ulonglong2*)(b2 + c0);
        ulonglong2 bB = *(const ulonglong2*)(b2 + c0 + 4);
#pragma unroll
        for (int i = 0; i < 4; i++) {
            acc2[i][0] = bA.x; acc2[i][1] = bA.y; acc2[i][2] = bB.x; acc2[i][3] = bB.y;
        }
    }
    for (int c = 0; c < 8; c++) {
        if (c < 7) {
            stage_w(wb + ((c + 1) & 1) * 2048, W2 + (c + 1) * 2048, tid);
            cp_commit(); cp_wait<1>();
        } else cp_wait<0>();
        __syncthreads();
        const float* w = wb + (c & 1) * 2048;
        int kb = c * 16;
#pragma unroll
        for (int k4 = 0; k4 < 16; k4 += 4) {
            float4 av[4];
#pragma unroll
            for (int i = 0; i < 4; i++)
                av[i] = *(const float4*)&s_hid[(e0 + i) * 128 + kb + k4];
#pragma unroll
            for (int kk = 0; kk < 4; kk++) {
                const float* wr = w + (k4 + kk) * 128 + c0;
                ulonglong2 w0 = *(const ulonglong2*)(wr);
                ulonglong2 w1 = *(const ulonglong2*)(wr + 4);
#pragma unroll
                for (int i = 0; i < 4; i++) {
                    float a = (kk == 0) ? av[i].x : (kk == 1) ? av[i].y :
                              (kk == 2) ? av[i].z : av[i].w;
                    ull ad = dup2(a);
                    acc2[i][0] = fma2(ad, w0.x, acc2[i][0]);
                    acc2[i][1] = fma2(ad, w0.y, acc2[i][1]);
                    acc2[i][2] = fma2(ad, w1.x, acc2[i][2]);
                    acc2[i][3] = fma2(ad, w1.y, acc2[i][3]);
                }
            }
        }
        __syncthreads();
    }

    // scatter (mean aggregation numerator)
#pragma unroll
    for (int i = 0; i < 4; i++) {
        int t = s_t[e0 + i];
        float2 p0 = unpack2(acc2[i][0]), p1 = unpack2(acc2[i][1]);
        float2 p2 = unpack2(acc2[i][2]), p3 = unpack2(acc2[i][3]);
        red4(&g_aggr[t * HIDN + c0],     make_float4(p0.x, p0.y, p1.x, p1.y));
        red4(&g_aggr[t * HIDN + c0 + 4], make_float4(p2.x, p2.y, p3.x, p3.y));
    }
}

// ============================================================================
// Node update: h = LN(h + MLP([h, aggr/deg])).  64 nodes/block, 256 threads.
// Same staged-W scheme.  SMEM: s_in[64][256] | wbuf[2][2048]  => 81920B
// ============================================================================
#define UPD_SMEM (64*256*4 + 2*2048*4)

__global__ void __launch_bounds__(256) update_kernel2(
        const float* W1, const float* b1,
        const float* W2, const float* b2,
        const float* gw, const float* gb) {
    extern __shared__ float sm[];
    float* s_in  = sm;                 // [64][256]
    float* wb    = sm + 64 * 256;      // [2][2048]
    float* s_hid = sm;                 // alias [64][128]

    int tid = threadIdx.x, lane = tid & 31, warp = tid >> 5;
    int nb = blockIdx.x * 64;

    stage_w(wb, W1, tid); cp_commit();

    // gather [h | aggr/deg]
    for (int j = warp; j < 64; j += 8) {
        int n = nb + j;
        if (n < NND) {
            float inv = g_invd[n];
            float4 hv = *(const float4*)&g_h[n * HIDN + 4 * lane];
            float4 av = *(const float4*)&g_aggr[n * HIDN + 4 * lane];
            av.x *= inv; av.y *= inv; av.z *= inv; av.w *= inv;
            *(float4*)&s_in[j * 256 + 4 * lane] = hv;
            *(float4*)&s_in[j * 256 + 128 + 4 * lane] = av;
        } else {
            *(float4*)&s_in[j * 256 + 4 * lane] = make_float4(0.f, 0.f, 0.f, 0.f);
            *(float4*)&s_in[j * 256 + 128 + 4 * lane] = make_float4(0.f, 0.f, 0.f, 0.f);
        }
    }

    int cg = tid & 15, egp = tid >> 4;
    int c0 = 8 * cg, e0 = 4 * egp;

    // ---------------- GEMM1: [64,256] @ [256,128], relu ----------------
    ull acc[4][4];
    {
        ulonglong2 bA = *(const ulonglong2*)(b1 + c0);
        ulonglong2 bB = *(const ulonglong2*)(b1 + c0 + 4);
#pragma unroll
        for (int i = 0; i < 4; i++) {
            acc[i][0] = bA.x; acc[i][1] = bA.y; acc[i][2] = bB.x; acc[i][3] = bB.y;
        }
    }
    for (int c = 0; c < 16; c++) {
        if (c < 15) {
            stage_w(wb + ((c + 1) & 1) * 2048, W1 + (c + 1) * 2048, tid);
            cp_commit(); cp_wait<1>();
        } else cp_wait<0>();
        __syncthreads();
        const float* w = wb + (c & 1) * 2048;
        int kb = c * 16;
#pragma unroll
        for (int k4 = 0; k4 < 16; k4 += 4) {
            float4 av[4];
#pragma unroll
            for (int i = 0; i < 4; i++)
                av[i] = *(const float4*)&s_in[(e0 + i) * 256 + kb + k4];
#pragma unroll
            for (int kk = 0; kk < 4; kk++) {
                const float* wr = w + (k4 + kk) * 128 + c0;
                ulonglong2 w0 = *(const ulonglong2*)(wr);
                ulonglong2 w1 = *(const ulonglong2*)(wr + 4);
#pragma unroll
                for (int i = 0; i < 4; i++) {
                    float a = (kk == 0) ? av[i].x : (kk == 1) ? av[i].y :
                              (kk == 2) ? av[i].z : av[i].w;
                    ull ad = dup2(a);
                    acc[i][0] = fma2(ad, w0.x, acc[i][0]);
                    acc[i][1] = fma2(ad, w0.y, acc[i][1]);
                    acc[i][2] = fma2(ad, w1.x, acc[i][2]);
                    acc[i][3] = fma2(ad, w1.y, acc[i][3]);
                }
            }
        }
        __syncthreads();
    }

    stage_w(wb, W2, tid); cp_commit();

#pragma unroll
    for (int i = 0; i < 4; i++) {
        float2 p0 = unpack2(acc[i][0]), p1 = unpack2(acc[i][1]);
        float2 p2 = unpack2(acc[i][2]), p3 = unpack2(acc[i][3]);
        *(float4*)&s_hid[(e0 + i) * 128 + c0] =
            make_float4(fmaxf(p0.x, 0.f), fmaxf(p0.y, 0.f), fmaxf(p1.x, 0.f), fmaxf(p1.y, 0.f));
        *(float4*)&s_hid[(e0 + i) * 128 + c0 + 4] =
            make_float4(fmaxf(p2.x, 0.f), fmaxf(p2.y, 0.f), fmaxf(p3.x, 0.f), fmaxf(p3.y, 0.f));
    }

    // ---------------- GEMM2: [64,128] @ [128,128] ----------------
    ull acc2[4][4];
    {
        ulonglong2 bA = *(const ulonglong2*)(b2 + c0);
        ulonglong2 bB = *(const ulonglong2*)(b2 + c0 + 4);
#pragma unroll
        for (int i = 0; i < 4; i++) {
            acc2[i][0] = bA.x; acc2[i][1] = bA.y; acc2[i][2] = bB.x; acc2[i][3] = bB.y;
        }
    }
    for (int c = 0; c < 8; c++) {
        if (c < 7) {
            stage_w(wb + ((c + 1) & 1) * 2048, W2 + (c + 1) * 2048, tid);
            cp_commit(); cp_wait<1>();
        } else cp_wait<0>();
        __syncthreads();
        const float* w = wb + (c & 1) * 2048;
        int kb = c * 16;
#pragma unroll
        for (int k4 = 0; k4 < 16; k4 += 4) {
            float4 av[4];
#pragma unroll
            for (int i = 0; i < 4; i++)
                av[i] = *(const float4*)&s_hid[(e0 + i) * 128 + kb + k4];
#pragma unroll
            for (int kk = 0; kk < 4; kk++) {
                const float* wr = w + (k4 + kk) * 128 + c0;
                ulonglong2 w0 = *(const ulonglong2*)(wr);
                ulonglong2 w1 = *(const ulonglong2*)(wr + 4);
#pragma unroll
                for (int i = 0; i < 4; i++) {
                    float a = (kk == 0) ? av[i].x : (kk == 1) ? av[i].y :
                              (kk == 2) ? av[i].z : av[i].w;
                    ull ad = dup2(a);
                    acc2[i][0] = fma2(ad, w0.x, acc2[i][0]);
                    acc2[i][1] = fma2(ad, w0.y, acc2[i][1]);
                    acc2[i][2] = fma2(ad, w1.x, acc2[i][2]);
                    acc2[i][3] = fma2(ad, w1.y, acc2[i][3]);
                }
            }
        }
        __syncthreads();
    }

    // residual + LayerNorm + store (16 lanes of a half-warp hold one node row)
    float4 g0 = *(const float4*)&gw[c0], g1 = *(const float4*)&gw[c0 + 4];
    float4 bb0 = *(const float4*)&gb[c0], bb1 = *(const float4*)&gb[c0 + 4];
#pragma unroll
    for (int i = 0; i < 4; i++) {
        int n = nb + e0 + i;
        float2 p0 = unpack2(acc2[i][0]), p1 = unpack2(acc2[i][1]);
        float2 p2 = unpack2(acc2[i][2]), p3 = unpack2(acc2[i][3]);
        float4 h0 = make_float4(0.f, 0.f, 0.f, 0.f), h1 = h0;
        if (n < NND) {
            h0 = *(const float4*)&g_h[n * HIDN + c0];
            h1 = *(const float4*)&g_h[n * HIDN + c0 + 4];
        }
        float o[8];
        o[0] = p0.x + h0.x; o[1] = p0.y + h0.y; o[2] = p1.x + h0.z; o[3] = p1.y + h0.w;
        o[4] = p2.x + h1.x; o[5] = p2.y + h1.y; o[6] = p3.x + h1.z; o[7] = p3.y + h1.w;
        float s = 0.f, q = 0.f;
#pragma unroll
        for (int k = 0; k < 8; k++) { s += o[k]; q += o[k] * o[k]; }
#pragma unroll
        for (int off = 1; off < 16; off <<= 1) {
            s += __shfl_xor_sync(0xffffffffu, s, off);
            q += __shfl_xor_sync(0xffffffffu, q, off);
        }
        float mean = s * (1.f / 128.f);
        float var  = q * (1.f / 128.f) - mean * mean;
        float rs   = rsqrtf(var + 1e-5f);
        if (n < NND) {
            float4 r0, r1;
            r0.x = (o[0] - mean) * rs * g0.x + bb0.x;
            r0.y = (o[1] - mean) * rs * g0.y + bb0.y;
            r0.z = (o[2] - mean) * rs * g0.z + bb0.z;
            r0.w = (o[3] - mean) * rs * g0.w + bb0.w;
            r1.x = (o[4] - mean) * rs * g1.x + bb1.x;
            r1.y = (o[5] - mean) * rs * g1.y + bb1.y;
            r1.z = (o[6] - mean) * rs * g1.z + bb1.z;
            r1.w = (o[7] - mean) * rs * g1.w + bb1.w;
            *(float4*)&g_h[n * HIDN + c0]     = r0;
            *(float4*)&g_h[n * HIDN + c0 + 4] = r1;
            *(float4*)&g_aggr[n * HIDN + c0]     = make_float4(0.f, 0.f, 0.f, 0.f);
            *(float4*)&g_aggr[n * HIDN + c0 + 4] = make_float4(0.f, 0.f, 0.f, 0.f);
        }
    }
}

// ---------------- layernorm + store helper (legacy node kernels) ----------
__device__ __forceinline__ void ln_store(float (*s_out)[HPAD], int nb,
                                         const float* gw, const float* gb) {
    int tid = threadIdx.x;
    int nn = tid >> 3;
    int p  = tid & 7;
    int n  = nb + nn;
    float vals[16];
    float sum = 0.f, sq = 0.f;
#pragma unroll
    for (int i = 0; i < 4; i++) {
        float4 t4 = *(float4*)&s_out[nn][16 * p + 4 * i];
        vals[4*i+0] = t4.x; vals[4*i+1] = t4.y; vals[4*i+2] = t4.z; vals[4*i+3] = t4.w;
        sum += t4.x + t4.y + t4.z + t4.w;
        sq  += t4.x*t4.x + t4.y*t4.y + t4.z*t4.z + t4.w*t4.w;
    }
#pragma unroll
    for (int off = 4; off; off >>= 1) {
        sum += __shfl_xor_sync(0xffffffffu, sum, off);
        sq  += __shfl_xor_sync(0xffffffffu, sq,  off);
    }
    float mean = sum * (1.f / 128.f);
    float var  = sq * (1.f / 128.f) - mean * mean;
    float rs   = rsqrtf(var + 1e-5f);
    if (n < NND) {
#pragma unroll
        for (int i = 0; i < 4; i++) {
            int c = 16 * p + 4 * i;
            float4 o;
            o.x = (vals[4*i+0] - mean) * rs * gw[c + 0] + gb[c + 0];
            o.y = (vals[4*i+1] - mean) * rs * gw[c + 1] + gb[c + 1];
            o.z = (vals[4*i+2] - mean) * rs * gw[c + 2] + gb[c + 2];
            o.w = (vals[4*i+3] - mean) * rs * gw[c + 3] + gb[c + 3];
            *(float4*)&g_h[n * HIDN + c] = o;
        }
    }
}

// ---------------- encoder: h = LN(relu(x @ W + b)) ----------------
__global__ __launch_bounds__(256) void encoder_kernel(const float* x, const float* W,
                                                      const float* b, const float* gw,
                                                      const float* gb) {
    __shared__ float s_in[TN][XPAD];
    __shared__ float s_out[TN][HPAD];
    int tid = threadIdx.x, lane = tid & 31, w = tid >> 5;
    int nb = blockIdx.x * TN;
    for (int j = w; j < TN; j += 8) {
        int n = nb + j;
        if (lane < 8) {
            float4 v = make_float4(0.f, 0.f, 0.f, 0.f);
            if (n < NND) v = *(const float4*)&x[n * NODE_IN + 4 * lane];
            *(float4*)&s_in[j][4 * lane] = v;
        }
    }
    __syncthreads();
    int cg = tid & 31, c0 = 4 * cg, eg = tid >> 5, e0 = 4 * eg;
    ull acc[4][2];
    {
        ull b01 = *(const ull*)(b + c0), b23 = *(const ull*)(b + c0 + 2);
#pragma unroll
        for (int i = 0; i < 4; i++) { acc[i][0] = b01; acc[i][1] = b23; }
    }
#pragma unroll
    for (int k = 0; k < NODE_IN; k++) {
        ulonglong2 wv = *(const ulonglong2*)(W + k * HIDN + c0);
#pragma unroll
        for (int i = 0; i < 4; i++) {
            ull a = dup2(s_in[e0 + i][k]);
            acc[i][0] = fma2(a, wv.x, acc[i][0]);
            acc[i][1] = fma2(a, wv.y, acc[i][1]);
        }
    }
#pragma unroll
    for (int i = 0; i < 4; i++) {
        float2 v0 = unpack2(acc[i][0]), v1 = unpack2(acc[i][1]);
        s_out[e0 + i][c0 + 0] = fmaxf(v0.x, 0.f);
        s_out[e0 + i][c0 + 1] = fmaxf(v0.y, 0.f);
        s_out[e0 + i][c0 + 2] = fmaxf(v1.x, 0.f);
        s_out[e0 + i][c0 + 3] = fmaxf(v1.y, 0.f);
    }
    __syncthreads();
    ln_store(s_out, nb, gw, gb);
}

// ---------------- head: out = h @ head_W + head_b ----------------
__global__ __launch_bounds__(256) void head_kernel(const float* W, const float* b,
                                                   float* out) {
    __shared__ float s_in[TN][HPAD];
    int tid = threadIdx.x, lane = tid & 31, w = tid >> 5;
    int nb = blockIdx.x * TN;
    for (int j = w; j < TN; j += 8) {
        int n = nb + j;
        float4 v = make_float4(0.f, 0.f, 0.f, 0.f);
        if (n < NND) v = *(const float4*)&g_h[n * HIDN + 4 * lane];
        *(float4*)&s_in[j][4 * lane] = v;
    }
    __syncthreads();
    int cg = tid & 31, c0 = 4 * cg, eg = tid >> 5, e0 = 4 * eg;
    ull acc[4][2];
    {
        ull b01 = *(const ull*)(b + c0), b23 = *(const ull*)(b + c0 + 2);
#pragma unroll
        for (int i = 0; i < 4; i++) { acc[i][0] = b01; acc[i][1] = b23; }
    }
#pragma unroll 4
    for (int k = 0; k < HIDN; k++) {
        ulonglong2 wv = *(const ulonglong2*)(W + k * HIDN + c0);
#pragma unroll
        for (int i = 0; i < 4; i++) {
            ull a = dup2(s_in[e0 + i][k]);
            acc[i][0] = fma2(a, wv.x, acc[i][0]);
            acc[i][1] = fma2(a, wv.y, acc[i][1]);
        }
    }
#pragma unroll
    for (int i = 0; i < 4; i++) {
        int n = nb + e0 + i;
        if (n < NND) {
            float2 v0 = unpack2(acc[i][0]), v1 = unpack2(acc[i][1]);
            *(float2*)&out[n * HIDN + c0 + 0] = v0;
            *(float2*)&out[n * HIDN + c0 + 2] = v1;
        }
    }
}

// ---------------- launch ----------------
extern "C" void kernel_launch(void* const* d_in, const int* in_sizes, int n_in,
                              void* d_out, int out_size) {
    const float* x      = (const float*)d_in[0];
    const void*  ei     = d_in[1];
    const float* ea     = (const float*)d_in[2];
    const float* enc_W  = (const float*)d_in[3];
    const float* enc_b  = (const float*)d_in[4];
    const float* enc_g  = (const float*)d_in[5];
    const float* enc_be = (const float*)d_in[6];
    const float* msg_W1 = (const float*)d_in[7];
    const float* msg_b1 = (const float*)d_in[8];
    const float* msg_W2 = (const float*)d_in[9];
    const float* msg_b2 = (const float*)d_in[10];
    const float* upd_W1 = (const float*)d_in[11];
    const float* upd_b1 = (const float*)d_in[12];
    const float* upd_W2 = (const float*)d_in[13];
    const float* upd_b2 = (const float*)d_in[14];
    const float* ln_g   = (const float*)d_in[15];
    const float* ln_be  = (const float*)d_in[16];
    const float* head_W = (const float*)d_in[17];
    const float* head_b = (const float*)d_in[18];
    float* out = (float*)d_out;

    cudaFuncSetAttribute(edge_kernel2, cudaFuncAttributeMaxDynamicSharedMemorySize, EDGE_SMEM);
    cudaFuncSetAttribute(update_kernel2, cudaFuncAttributeMaxDynamicSharedMemorySize, UPD_SMEM);

    init_kernel<<<256, 256>>>();
    detect_kernel<<<256, 256>>>((const unsigned*)ei);
    count_kernel<<<512, 256>>>(ei);
    inv_kernel<<<(NND + 255) / 256, 256>>>();

    int nblk32 = (NND + TN - 1) / TN;
    int nblk64 = (NND + 63) / 64;
    encoder_kernel<<<nblk32, 256>>>(x, enc_W, enc_b, enc_g, enc_be);

    for (int l = 0; l < 2; l++) {
        edge_kernel2<<<NE / 64, 256, EDGE_SMEM>>>(ei, ea,
                                      msg_W1 + l * CIN * HIDN, msg_b1 + l * HIDN,
                                      msg_W2 + l * HIDN * HIDN, msg_b2 + l * HIDN);
        update_kernel2<<<nblk64, 256, UPD_SMEM>>>(upd_W1 + l * UIN * HIDN, upd_b1 + l * HIDN,
                                     upd_W2 + l * HIDN * HIDN, upd_b2 + l * HIDN,
                                     ln_g + l * HIDN, ln_be + l * HIDN);
    }
    head_kernel<<<nblk32, 256>>>(head_W, head_b, out);
}

// round 4
// speedup vs baseline: 1.5534x; 1.3656x over previous
#include <cuda_runtime.h>
#include <math.h>

#define NND 50000
#define NE  800000
#define HIDN 128
#define NODE_IN 32
#define EDGE_IN 16
#define CIN 272        // 2*HID + EDGE_IN
#define UIN 256        // 2*HID
#define HPAD 132
#define XPAD 36
#define TN 32

typedef unsigned long long ull;

// ---------------- persistent scratch ----------------
__device__ float g_h[NND * HIDN];
__device__ float g_aggr[NND * HIDN];
__device__ float g_invd[NND];
__device__ int   g_cnt[NND];
__device__ int   g_is64;

// ---------------- packed f32x2 helpers ----------------
__device__ __forceinline__ ull fma2(ull a, ull b, ull c) {
    ull d;
    asm("fma.rn.f32x2 %0, %1, %2, %3;" : "=l"(d) : "l"(a), "l"(b), "l"(c));
    return d;
}
__device__ __forceinline__ ull dup2(float a) {
    ull d; unsigned r = __float_as_uint(a);
    asm("mov.b64 %0, {%1, %1};" : "=l"(d) : "r"(r));
    return d;
}
__device__ __forceinline__ float2 unpack2(ull v) {
    unsigned lo, hi;
    asm("mov.b64 {%0, %1}, %2;" : "=r"(lo), "=r"(hi) : "l"(v));
    return make_float2(__uint_as_float(lo), __uint_as_float(hi));
}

// ---------------- async copy helpers ----------------
__device__ __forceinline__ void cp16(float* dst_smem, const float* src) {
    unsigned d = (unsigned)__cvta_generic_to_shared(dst_smem);
    asm volatile("cp.async.ca.shared.global [%0], [%1], 16;" :: "r"(d), "l"(src));
}
__device__ __forceinline__ void cp_commit() {
    asm volatile("cp.async.commit_group;");
}
template<int N> __device__ __forceinline__ void cp_wait() {
    asm volatile("cp.async.wait_group %0;" :: "n"(N));
}
// stage one 16x128 fp32 W chunk (2048 floats) with 128 threads (16 floats each)
__device__ __forceinline__ void stage_w128(float* dst, const float* src, int tid) {
    int o = tid * 16;
    cp16(dst + o,      src + o);
    cp16(dst + o + 4,  src + o + 4);
    cp16(dst + o + 8,  src + o + 8);
    cp16(dst + o + 12, src + o + 12);
}

// vector reduction into global (fp32 x4)
__device__ __forceinline__ void red4(float* addr, float4 v) {
    asm volatile("red.global.add.v4.f32 [%0], {%1, %2, %3, %4};"
                 :: "l"(addr), "f"(v.x), "f"(v.y), "f"(v.z), "f"(v.w) : "memory");
}

// ---------------- edge index (int32/int64 runtime-detected) ----------------
__device__ __forceinline__ void load_edge(const void* ei, int e, int& s, int& t) {
    if (g_is64) {
        const long long* p = (const long long*)ei;
        s = (int)p[e];
        t = (int)p[NE + e];
    } else {
        const int* p = (const int*)ei;
        s = p[e];
        t = p[NE + e];
    }
}

// ---------------- setup kernels ----------------
__global__ void init_kernel() {
    int i = blockIdx.x * blockDim.x + threadIdx.x;
    int stride = gridDim.x * blockDim.x;
    if (i == 0) g_is64 = 1;
    for (int j = i; j < NND; j += stride) g_cnt[j] = 0;
    for (int j = i; j < NND * HIDN; j += stride) g_aggr[j] = 0.f;
}
__global__ void detect_kernel(const unsigned* w) {
    int stride = gridDim.x * blockDim.x;
    bool nz = false;
    for (int i = blockIdx.x * blockDim.x + threadIdx.x; i < NE; i += stride)
        nz |= (w[2 * i + 1] != 0u);
    if (nz) g_is64 = 0;
}
__global__ void count_kernel(const void* ei) {
    int stride = gridDim.x * blockDim.x;
    for (int e = blockIdx.x * blockDim.x + threadIdx.x; e < NE; e += stride) {
        int s, t; load_edge(ei, e, s, t);
        atomicAdd(&g_cnt[t], 1);
    }
}
__global__ void inv_kernel() {
    int n = blockIdx.x * blockDim.x + threadIdx.x;
    if (n < NND) g_invd[n] = 1.f / fmaxf((float)g_cnt[n], 1.f);
}

// ============================================================================
// Fused edge MLP + scatter.  64 edges/block, 128 threads.
// Register tile: 8 edges x 8 channels/thread.  W staged in smem (cp.async x2),
// single-sync software pipeline:  wait; sync; stage(c+1); compute(c)
// SMEM: s_in[64][272] | wbuf[2][2048] | s_t[64]  => 86272B  (2 blocks/SM)
// ============================================================================
#define EDGE_SMEM (64*272*4 + 2*2048*4 + 64*4)

__global__ void __launch_bounds__(128) edge_kernel2(
        const void* ei, const float* ea,
        const float* W1, const float* b1,
        const float* W2, const float* b2) {
    extern __shared__ float sm[];
    float* s_in  = sm;                       // [64][272]
    float* wb    = sm + 64 * 272;            // [2][2048]
    int*   s_t   = (int*)(sm + 64 * 272 + 2 * 2048);
    float* s_hid = sm;                       // alias [64][128]

    int tid = threadIdx.x, lane = tid & 31, warp = tid >> 5;
    int eb = blockIdx.x * 64;

    // prefetch W1 chunk 0 (overlaps gather)
    stage_w128(wb, W1, tid); cp_commit();

    // gather [x_i | x_j | edge_attr]
    for (int j = warp; j < 64; j += 4) {
        int e = eb + j, s, t;
        load_edge(ei, e, s, t);
        if (lane == 0) s_t[j] = t;
        *(float4*)&s_in[j * 272 + 4 * lane]       = *(const float4*)&g_h[t * HIDN + 4 * lane];
        *(float4*)&s_in[j * 272 + 128 + 4 * lane] = *(const float4*)&g_h[s * HIDN + 4 * lane];
        if (lane < 4)
            *(float4*)&s_in[j * 272 + 256 + 4 * lane] =
                *(const float4*)&ea[(size_t)e * EDGE_IN + 4 * lane];
    }

    int cg = tid & 15, egp = tid >> 4;     // 16 channel groups x 8 edge groups
    int c0 = 8 * cg, e0 = 8 * egp;

    // ---------------- GEMM1: [64,272] @ [272,128], relu ----------------
    ull acc[8][4];
    {
        ulonglong2 bA = *(const ulonglong2*)(b1 + c0);
        ulonglong2 bB = *(const ulonglong2*)(b1 + c0 + 4);
#pragma unroll
        for (int i = 0; i < 8; i++) {
            acc[i][0] = bA.x; acc[i][1] = bA.y; acc[i][2] = bB.x; acc[i][3] = bB.y;
        }
    }
    for (int c = 0; c < 17; c++) {
        cp_wait<0>();
        __syncthreads();                 // chunk c ready; prev chunk reads done
        if (c < 16) { stage_w128(wb + ((c + 1) & 1) * 2048, W1 + (c + 1) * 2048, tid); cp_commit(); }
        const float* w = wb + (c & 1) * 2048;
        int kb = c * 16;
#pragma unroll
        for (int k4 = 0; k4 < 16; k4 += 4) {
            float4 av[8];
#pragma unroll
            for (int i = 0; i < 8; i++)
                av[i] = *(const float4*)&s_in[(e0 + i) * 272 + kb + k4];
#pragma unroll
            for (int kk = 0; kk < 4; kk++) {
                const float* wr = w + (k4 + kk) * 128 + c0;
                ulonglong2 w0 = *(const ulonglong2*)(wr);
                ulonglong2 w1 = *(const ulonglong2*)(wr + 4);
#pragma unroll
                for (int i = 0; i < 8; i++) {
                    float a = (kk == 0) ? av[i].x : (kk == 1) ? av[i].y :
                              (kk == 2) ? av[i].z : av[i].w;
                    ull ad = dup2(a);
                    acc[i][0] = fma2(ad, w0.x, acc[i][0]);
                    acc[i][1] = fma2(ad, w0.y, acc[i][1]);
                    acc[i][2] = fma2(ad, w1.x, acc[i][2]);
                    acc[i][3] = fma2(ad, w1.y, acc[i][3]);
                }
            }
        }
    }
    __syncthreads();                     // last chunk reads done before s_hid alias write

    // prefetch W2 chunk 0 into buf0 (safe: all W1 reads complete)
    stage_w128(wb, W2, tid); cp_commit();

    // relu -> s_hid (aliases s_in)
#pragma unroll
    for (int i = 0; i < 8; i++) {
        float2 p0 = unpack2(acc[i][0]), p1 = unpack2(acc[i][1]);
        float2 p2 = unpack2(acc[i][2]), p3 = unpack2(acc[i][3]);
        *(float4*)&s_hid[(e0 + i) * 128 + c0] =
            make_float4(fmaxf(p0.x, 0.f), fmaxf(p0.y, 0.f), fmaxf(p1.x, 0.f), fmaxf(p1.y, 0.f));
        *(float4*)&s_hid[(e0 + i) * 128 + c0 + 4] =
            make_float4(fmaxf(p2.x, 0.f), fmaxf(p2.y, 0.f), fmaxf(p3.x, 0.f), fmaxf(p3.y, 0.f));
    }

    // ---------------- GEMM2: [64,128] @ [128,128] ----------------
    ull acc2[8][4];
    {
        ulonglong2 bA = *(const ulonglong2*)(b2 + c0);
        ulonglong2 bB = *(const ulonglong2*)(b2 + c0 + 4);
#pragma unroll
        for (int i = 0; i < 8; i++) {
            acc2[i][0] = bA.x; acc2[i][1] = bA.y; acc2[i][2] = bB.x; acc2[i][3] = bB.y;
        }
    }
    for (int c = 0; c < 8; c++) {
        cp_wait<0>();
        __syncthreads();                 // also covers s_hid writes on c==0
        if (c < 7) { stage_w128(wb + ((c + 1) & 1) * 2048, W2 + (c + 1) * 2048, tid); cp_commit(); }
        const float* w = wb + (c & 1) * 2048;
        int kb = c * 16;
#pragma unroll
        for (int k4 = 0; k4 < 16; k4 += 4) {
            float4 av[8];
#pragma unroll
            for (int i = 0; i < 8; i++)
                av[i] = *(const float4*)&s_hid[(e0 + i) * 128 + kb + k4];
#pragma unroll
            for (int kk = 0; kk < 4; kk++) {
                const float* wr = w + (k4 + kk) * 128 + c0;
                ulonglong2 w0 = *(const ulonglong2*)(wr);
                ulonglong2 w1 = *(const ulonglong2*)(wr + 4);
#pragma unroll
                for (int i = 0; i < 8; i++) {
                    float a = (kk == 0) ? av[i].x : (kk == 1) ? av[i].y :
                              (kk == 2) ? av[i].z : av[i].w;
                    ull ad = dup2(a);
                    acc2[i][0] = fma2(ad, w0.x, acc2[i][0]);
                    acc2[i][1] = fma2(ad, w0.y, acc2[i][1]);
                    acc2[i][2] = fma2(ad, w1.x, acc2[i][2]);
                    acc2[i][3] = fma2(ad, w1.y, acc2[i][3]);
                }
            }
        }
    }

    // scatter (mean aggregation numerator)
#pragma unroll
    for (int i = 0; i < 8; i++) {
        int t = s_t[e0 + i];
        float2 p0 = unpack2(acc2[i][0]), p1 = unpack2(acc2[i][1]);
        float2 p2 = unpack2(acc2[i][2]), p3 = unpack2(acc2[i][3]);
        red4(&g_aggr[t * HIDN + c0],     make_float4(p0.x, p0.y, p1.x, p1.y));
        red4(&g_aggr[t * HIDN + c0 + 4], make_float4(p2.x, p2.y, p3.x, p3.y));
    }
}

// ============================================================================
// Node update: h = LN(h + MLP([h, aggr/deg])).  64 nodes/block, 128 threads,
// 8 nodes x 8 channels/thread, single-sync pipeline.
// SMEM: s_in[64][256] | wbuf[2][2048]  => 81920B
// ============================================================================
#define UPD_SMEM (64*256*4 + 2*2048*4)

__global__ void __launch_bounds__(128) update_kernel2(
        const float* W1, const float* b1,
        const float* W2, const float* b2,
        const float* gw, const float* gb) {
    extern __shared__ float sm[];
    float* s_in  = sm;                 // [64][256]
    float* wb    = sm + 64 * 256;      // [2][2048]
    float* s_hid = sm;                 // alias [64][128]

    int tid = threadIdx.x, lane = tid & 31, warp = tid >> 5;
    int nb = blockIdx.x * 64;

    stage_w128(wb, W1, tid); cp_commit();

    // gather [h | aggr/deg]
    for (int j = warp; j < 64; j += 4) {
        int n = nb + j;
        if (n < NND) {
            float inv = g_invd[n];
            float4 hv = *(const float4*)&g_h[n * HIDN + 4 * lane];
            float4 av = *(const float4*)&g_aggr[n * HIDN + 4 * lane];
            av.x *= inv; av.y *= inv; av.z *= inv; av.w *= inv;
            *(float4*)&s_in[j * 256 + 4 * lane] = hv;
            *(float4*)&s_in[j * 256 + 128 + 4 * lane] = av;
        } else {
            *(float4*)&s_in[j * 256 + 4 * lane] = make_float4(0.f, 0.f, 0.f, 0.f);
            *(float4*)&s_in[j * 256 + 128 + 4 * lane] = make_float4(0.f, 0.f, 0.f, 0.f);
        }
    }

    int cg = tid & 15, egp = tid >> 4;
    int c0 = 8 * cg, e0 = 8 * egp;

    // ---------------- GEMM1: [64,256] @ [256,128], relu ----------------
    ull acc[8][4];
    {
        ulonglong2 bA = *(const ulonglong2*)(b1 + c0);
        ulonglong2 bB = *(const ulonglong2*)(b1 + c0 + 4);
#pragma unroll
        for (int i = 0; i < 8; i++) {
            acc[i][0] = bA.x; acc[i][1] = bA.y; acc[i][2] = bB.x; acc[i][3] = bB.y;
        }
    }
    for (int c = 0; c < 16; c++) {
        cp_wait<0>();
        __syncthreads();
        if (c < 15) { stage_w128(wb + ((c + 1) & 1) * 2048, W1 + (c + 1) * 2048, tid); cp_commit(); }
        const float* w = wb + (c & 1) * 2048;
        int kb = c * 16;
#pragma unroll
        for (int k4 = 0; k4 < 16; k4 += 4) {
            float4 av[8];
#pragma unroll
            for (int i = 0; i < 8; i++)
                av[i] = *(const float4*)&s_in[(e0 + i) * 256 + kb + k4];
#pragma unroll
            for (int kk = 0; kk < 4; kk++) {
                const float* wr = w + (k4 + kk) * 128 + c0;
                ulonglong2 w0 = *(const ulonglong2*)(wr);
                ulonglong2 w1 = *(const ulonglong2*)(wr + 4);
#pragma unroll
                for (int i = 0; i < 8; i++) {
                    float a = (kk == 0) ? av[i].x : (kk == 1) ? av[i].y :
                              (kk == 2) ? av[i].z : av[i].w;
                    ull ad = dup2(a);
                    acc[i][0] = fma2(ad, w0.x, acc[i][0]);
                    acc[i][1] = fma2(ad, w0.y, acc[i][1]);
                    acc[i][2] = fma2(ad, w1.x, acc[i][2]);
                    acc[i][3] = fma2(ad, w1.y, acc[i][3]);
                }
            }
        }
    }
    __syncthreads();

    stage_w128(wb, W2, tid); cp_commit();

#pragma unroll
    for (int i = 0; i < 8; i++) {
        float2 p0 = unpack2(acc[i][0]), p1 = unpack2(acc[i][1]);
        float2 p2 = unpack2(acc[i][2]), p3 = unpack2(acc[i][3]);
        *(float4*)&s_hid[(e0 + i) * 128 + c0] =
            make_float4(fmaxf(p0.x, 0.f), fmaxf(p0.y, 0.f), fmaxf(p1.x, 0.f), fmaxf(p1.y, 0.f));
        *(float4*)&s_hid[(e0 + i) * 128 + c0 + 4] =
            make_float4(fmaxf(p2.x, 0.f), fmaxf(p2.y, 0.f), fmaxf(p3.x, 0.f), fmaxf(p3.y, 0.f));
    }

    // ---------------- GEMM2: [64,128] @ [128,128] ----------------
    ull acc2[8][4];
    {
        ulonglong2 bA = *(const ulonglong2*)(b2 + c0);
        ulonglong2 bB = *(const ulonglong2*)(b2 + c0 + 4);
#pragma unroll
        for (int i = 0; i < 8; i++) {
            acc2[i][0] = bA.x; acc2[i][1] = bA.y; acc2[i][2] = bB.x; acc2[i][3] = bB.y;
        }
    }
    for (int c = 0; c < 8; c++) {
        cp_wait<0>();
        __syncthreads();
        if (c < 7) { stage_w128(wb + ((c + 1) & 1) * 2048, W2 + (c + 1) * 2048, tid); cp_commit(); }
        const float* w = wb + (c & 1) * 2048;
        int kb = c * 16;
#pragma unroll
        for (int k4 = 0; k4 < 16; k4 += 4) {
            float4 av[8];
#pragma unroll
            for (int i = 0; i < 8; i++)
                av[i] = *(const float4*)&s_hid[(e0 + i) * 128 + kb + k4];
#pragma unroll
            for (int kk = 0; kk < 4; kk++) {
                const float* wr = w + (k4 + kk) * 128 + c0;
                ulonglong2 w0 = *(const ulonglong2*)(wr);
                ulonglong2 w1 = *(const ulonglong2*)(wr + 4);
#pragma unroll
                for (int i = 0; i < 8; i++) {
                    float a = (kk == 0) ? av[i].x : (kk == 1) ? av[i].y :
                              (kk == 2) ? av[i].z : av[i].w;
                    ull ad = dup2(a);
                    acc2[i][0] = fma2(ad, w0.x, acc2[i][0]);
                    acc2[i][1] = fma2(ad, w0.y, acc2[i][1]);
                    acc2[i][2] = fma2(ad, w1.x, acc2[i][2]);
                    acc2[i][3] = fma2(ad, w1.y, acc2[i][3]);
                }
            }
        }
    }

    // residual + LayerNorm + store (16 threads of a half-warp hold one node row)
    float4 g0 = *(const float4*)&gw[c0], g1 = *(const float4*)&gw[c0 + 4];
    float4 bb0 = *(const float4*)&gb[c0], bb1 = *(const float4*)&gb[c0 + 4];
#pragma unroll
    for (int i = 0; i < 8; i++) {
        int n = nb + e0 + i;
        float2 p0 = unpack2(acc2[i][0]), p1 = unpack2(acc2[i][1]);
        float2 p2 = unpack2(acc2[i][2]), p3 = unpack2(acc2[i][3]);
        float4 h0 = make_float4(0.f, 0.f, 0.f, 0.f), h1 = h0;
        if (n < NND) {
            h0 = *(const float4*)&g_h[n * HIDN + c0];
            h1 = *(const float4*)&g_h[n * HIDN + c0 + 4];
        }
        float o[8];
        o[0] = p0.x + h0.x; o[1] = p0.y + h0.y; o[2] = p1.x + h0.z; o[3] = p1.y + h0.w;
        o[4] = p2.x + h1.x; o[5] = p2.y + h1.y; o[6] = p3.x + h1.z; o[7] = p3.y + h1.w;
        float s = 0.f, q = 0.f;
#pragma unroll
        for (int k = 0; k < 8; k++) { s += o[k]; q += o[k] * o[k]; }
#pragma unroll
        for (int off = 1; off < 16; off <<= 1) {
            s += __shfl_xor_sync(0xffffffffu, s, off);
            q += __shfl_xor_sync(0xffffffffu, q, off);
        }
        float mean = s * (1.f / 128.f);
        float var  = q * (1.f / 128.f) - mean * mean;
        float rs   = rsqrtf(var + 1e-5f);
        if (n < NND) {
            float4 r0, r1;
            r0.x = (o[0] - mean) * rs * g0.x + bb0.x;
            r0.y = (o[1] - mean) * rs * g0.y + bb0.y;
            r0.z = (o[2] - mean) * rs * g0.z + bb0.z;
            r0.w = (o[3] - mean) * rs * g0.w + bb0.w;
            r1.x = (o[4] - mean) * rs * g1.x + bb1.x;
            r1.y = (o[5] - mean) * rs * g1.y + bb1.y;
            r1.z = (o[6] - mean) * rs * g1.z + bb1.z;
            r1.w = (o[7] - mean) * rs * g1.w + bb1.w;
            *(float4*)&g_h[n * HIDN + c0]     = r0;
            *(float4*)&g_h[n * HIDN + c0 + 4] = r1;
            *(float4*)&g_aggr[n * HIDN + c0]     = make_float4(0.f, 0.f, 0.f, 0.f);
            *(float4*)&g_aggr[n * HIDN + c0 + 4] = make_float4(0.f, 0.f, 0.f, 0.f);
        }
    }
}

// ---------------- layernorm + store helper (legacy node kernels) ----------
__device__ __forceinline__ void ln_store(float (*s_out)[HPAD], int nb,
                                         const float* gw, const float* gb) {
    int tid = threadIdx.x;
    int nn = tid >> 3;
    int p  = tid & 7;
    int n  = nb + nn;
    float vals[16];
    float sum = 0.f, sq = 0.f;
#pragma unroll
    for (int i = 0; i < 4; i++) {
        float4 t4 = *(float4*)&s_out[nn][16 * p + 4 * i];
        vals[4*i+0] = t4.x; vals[4*i+1] = t4.y; vals[4*i+2] = t4.z; vals[4*i+3] = t4.w;
        sum += t4.x + t4.y + t4.z + t4.w;
        sq  += t4.x*t4.x + t4.y*t4.y + t4.z*t4.z + t4.w*t4.w;
    }
#pragma unroll
    for (int off = 4; off; off >>= 1) {
        sum += __shfl_xor_sync(0xffffffffu, sum, off);
        sq  += __shfl_xor_sync(0xffffffffu, sq,  off);
    }
    float mean = sum * (1.f / 128.f);
    float var  = sq * (1.f / 128.f) - mean * mean;
    float rs   = rsqrtf(var + 1e-5f);
    if (n < NND) {
#pragma unroll
        for (int i = 0; i < 4; i++) {
            int c = 16 * p + 4 * i;
            float4 o;
            o.x = (vals[4*i+0] - mean) * rs * gw[c + 0] + gb[c + 0];
            o.y = (vals[4*i+1] - mean) * rs * gw[c + 1] + gb[c + 1];
            o.z = (vals[4*i+2] - mean) * rs * gw[c + 2] + gb[c + 2];
            o.w = (vals[4*i+3] - mean) * rs * gw[c + 3] + gb[c + 3];
            *(float4*)&g_h[n * HIDN + c] = o;
        }
    }
}

// ---------------- encoder: h = LN(relu(x @ W + b)) ----------------
__global__ __launch_bounds__(256) void encoder_kernel(const float* x, const float* W,
                                                      const float* b, const float* gw,
                                                      const float* gb) {
    __shared__ float s_in[TN][XPAD];
    __shared__ float s_out[TN][HPAD];
    int tid = threadIdx.x, lane = tid & 31, w = tid >> 5;
    int nb = blockIdx.x * TN;
    for (int j = w; j < TN; j += 8) {
        int n = nb + j;
        if (lane < 8) {
            float4 v = make_float4(0.f, 0.f, 0.f, 0.f);
            if (n < NND) v = *(const float4*)&x[n * NODE_IN + 4 * lane];
            *(float4*)&s_in[j][4 * lane] = v;
        }
    }
    __syncthreads();
    int cg = tid & 31, c0 = 4 * cg, eg = tid >> 5, e0 = 4 * eg;
    ull acc[4][2];
    {
        ull b01 = *(const ull*)(b + c0), b23 = *(const ull*)(b + c0 + 2);
#pragma unroll
        for (int i = 0; i < 4; i++) { acc[i][0] = b01; acc[i][1] = b23; }
    }
#pragma unroll
    for (int k = 0; k < NODE_IN; k++) {
        ulonglong2 wv = *(const ulonglong2*)(W + k * HIDN + c0);
#pragma unroll
        for (int i = 0; i < 4; i++) {
            ull a = dup2(s_in[e0 + i][k]);
            acc[i][0] = fma2(a, wv.x, acc[i][0]);
            acc[i][1] = fma2(a, wv.y, acc[i][1]);
        }
    }
#pragma unroll
    for (int i = 0; i < 4; i++) {
        float2 v0 = unpack2(acc[i][0]), v1 = unpack2(acc[i][1]);
        s_out[e0 + i][c0 + 0] = fmaxf(v0.x, 0.f);
        s_out[e0 + i][c0 + 1] = fmaxf(v0.y, 0.f);
        s_out[e0 + i][c0 + 2] = fmaxf(v1.x, 0.f);
        s_out[e0 + i][c0 + 3] = fmaxf(v1.y, 0.f);
    }
    __syncthreads();
    ln_store(s_out, nb, gw, gb);
}

// ---------------- head: out = h @ head_W + head_b ----------------
__global__ __launch_bounds__(256) void head_kernel(const float* W, const float* b,
                                                   float* out) {
    __shared__ float s_in[TN][HPAD];
    int tid = threadIdx.x, lane = tid & 31, w = tid >> 5;
    int nb = blockIdx.x * TN;
    for (int j = w; j < TN; j += 8) {
        int n = nb + j;
        float4 v = make_float4(0.f, 0.f, 0.f, 0.f);
        if (n < NND) v = *(const float4*)&g_h[n * HIDN + 4 * lane];
        *(float4*)&s_in[j][4 * lane] = v;
    }
    __syncthreads();
    int cg = tid & 31, c0 = 4 * cg, eg = tid >> 5, e0 = 4 * eg;
    ull acc[4][2];
    {
        ull b01 = *(const ull*)(b + c0), b23 = *(const ull*)(b + c0 + 2);
#pragma unroll
        for (int i = 0; i < 4; i++) { acc[i][0] = b01; acc[i][1] = b23; }
    }
#pragma unroll 4
    for (int k = 0; k < HIDN; k++) {
        ulonglong2 wv = *(const ulonglong2*)(W + k * HIDN + c0);
#pragma unroll
        for (int i = 0; i < 4; i++) {
            ull a = dup2(s_in[e0 + i][k]);
            acc[i][0] = fma2(a, wv.x, acc[i][0]);
            acc[i][1] = fma2(a, wv.y, acc[i][1]);
        }
    }
#pragma unroll
    for (int i = 0; i < 4; i++) {
        int n = nb + e0 + i;
        if (n < NND) {
            float2 v0 = unpack2(acc[i][0]), v1 = unpack2(acc[i][1]);
            *(float2*)&out[n * HIDN + c0 + 0] = v0;
            *(float2*)&out[n * HIDN + c0 + 2] = v1;
        }
    }
}

// ---------------- launch ----------------
extern "C" void kernel_launch(void* const* d_in, const int* in_sizes, int n_in,
                              void* d_out, int out_size) {
    const float* x      = (const float*)d_in[0];
    const void*  ei     = d_in[1];
    const float* ea     = (const float*)d_in[2];
    const float* enc_W  = (const float*)d_in[3];
    const float* enc_b  = (const float*)d_in[4];
    const float* enc_g  = (const float*)d_in[5];
    const float* enc_be = (const float*)d_in[6];
    const float* msg_W1 = (const float*)d_in[7];
    const float* msg_b1 = (const float*)d_in[8];
    const float* msg_W2 = (const float*)d_in[9];
    const float* msg_b2 = (const float*)d_in[10];
    const float* upd_W1 = (const float*)d_in[11];
    const float* upd_b1 = (const float*)d_in[12];
    const float* upd_W2 = (const float*)d_in[13];
    const float* upd_b2 = (const float*)d_in[14];
    const float* ln_g   = (const float*)d_in[15];
    const float* ln_be  = (const float*)d_in[16];
    const float* head_W = (const float*)d_in[17];
    const float* head_b = (const float*)d_in[18];
    float* out = (float*)d_out;

    cudaFuncSetAttribute(edge_kernel2, cudaFuncAttributeMaxDynamicSharedMemorySize, EDGE_SMEM);
    cudaFuncSetAttribute(update_kernel2, cudaFuncAttributeMaxDynamicSharedMemorySize, UPD_SMEM);

    init_kernel<<<256, 256>>>();
    detect_kernel<<<256, 256>>>((const unsigned*)ei);
    count_kernel<<<512, 256>>>(ei);
    inv_kernel<<<(NND + 255) / 256, 256>>>();

    int nblk32 = (NND + TN - 1) / TN;
    int nblk64 = (NND + 63) / 64;
    encoder_kernel<<<nblk32, 256>>>(x, enc_W, enc_b, enc_g, enc_be);

    for (int l = 0; l < 2; l++) {
        edge_kernel2<<<NE / 64, 128, EDGE_SMEM>>>(ei, ea,
                                      msg_W1 + l * CIN * HIDN, msg_b1 + l * HIDN,
                                      msg_W2 + l * HIDN * HIDN, msg_b2 + l * HIDN);
        update_kernel2<<<nblk64, 128, UPD_SMEM>>>(upd_W1 + l * UIN * HIDN, upd_b1 + l * HIDN,
                                     upd_W2 + l * HIDN * HIDN, upd_b2 + l * HIDN,
                                     ln_g + l * HIDN, ln_be + l * HIDN);
    }
    head_kernel<<<nblk32, 256>>>(head_W, head_b, out);
}